// round 1
// baseline (speedup 1.0000x reference)
#include <cuda_runtime.h>
#include <cuda_bf16.h>

// Problem constants
#define BB 2
#define SS 2048
#define DD 128
#define HH 8
#define HDIM 16
#define DFF 512
#define MROWS (BB*SS)   // 4096

// ---------------- scratch (device globals; no allocation allowed) -------------
__device__ float g_q[BB*HH*SS*HDIM];
__device__ float g_k[BB*HH*SS*HDIM];
__device__ float g_v[BB*HH*SS*HDIM];
__device__ float g_attn[BB*SS*DD];
__device__ float g_r1[BB*SS*DD];
__device__ float g_r2[BB*SS*DD];
__device__ float g_ln[BB*SS*DD];
__device__ float g_h[BB*SS*DFF];

// ---------------- packed f32x2 helpers (B300 2x fp32 path) --------------------
__device__ __forceinline__ unsigned long long pack2(float lo, float hi) {
    unsigned long long r;
    asm("mov.b64 %0, {%1, %2};" : "=l"(r)
        : "r"(__float_as_uint(lo)), "r"(__float_as_uint(hi)));
    return r;
}
__device__ __forceinline__ void unpack2(unsigned long long p, float& lo, float& hi) {
    unsigned int a, b;
    asm("mov.b64 {%0, %1}, %2;" : "=r"(a), "=r"(b) : "l"(p));
    lo = __uint_as_float(a); hi = __uint_as_float(b);
}
__device__ __forceinline__ unsigned long long fma2(unsigned long long a,
                                                   unsigned long long b,
                                                   unsigned long long c) {
    unsigned long long d;
    asm("fma.rn.f32x2 %0, %1, %2, %3;" : "=l"(d) : "l"(a), "l"(b), "l"(c));
    return d;
}

// ---------------- generic tiled GEMM:  out = A(MxK) @ W(KxN) + epilogue -------
// EPI: 0 = plain store
//      1 = + bias[c] + res[r*N+c]
//      2 = relu(+ bias[c])
//      3 = scatter into head layout [b][h][s][hd], col c -> h=c&7, hd=c>>3
template<int K, int N, int EPI>
__global__ void __launch_bounds__(256) gemm_kernel(
    const float* __restrict__ A, const float* __restrict__ W,
    const float* __restrict__ bias, const float* __restrict__ res,
    float* __restrict__ out)
{
    __shared__ float As[32][64];
    __shared__ float Ws[32][64];
    const int tid = threadIdx.x;
    const int tx = tid & 15, ty = tid >> 4;
    const int bm = blockIdx.y * 64, bn = blockIdx.x * 64;

    float acc[4][4] = {};

    for (int kt = 0; kt < K; kt += 32) {
        // A tile: 64 rows x 32 k (transposed into As[k][m])
#pragma unroll
        for (int i = 0; i < 2; i++) {
            int idx = tid * 2 + i;            // 0..511
            int row = idx >> 3;
            int kc  = (idx & 7) * 4;
            float4 t = *(const float4*)&A[(size_t)(bm + row) * K + kt + kc];
            As[kc + 0][row] = t.x; As[kc + 1][row] = t.y;
            As[kc + 2][row] = t.z; As[kc + 3][row] = t.w;
        }
        // W tile: 32 k x 64 cols
#pragma unroll
        for (int i = 0; i < 2; i++) {
            int idx = tid * 2 + i;
            int r = idx >> 4;                 // 0..31
            int c = (idx & 15) * 4;
            *(float4*)&Ws[r][c] = *(const float4*)&W[(size_t)(kt + r) * N + bn + c];
        }
        __syncthreads();
#pragma unroll
        for (int kk = 0; kk < 32; kk++) {
            float4 a4 = *(const float4*)&As[kk][ty * 4];
            float4 b4 = *(const float4*)&Ws[kk][tx * 4];
            float av[4] = {a4.x, a4.y, a4.z, a4.w};
            float bv[4] = {b4.x, b4.y, b4.z, b4.w};
#pragma unroll
            for (int i = 0; i < 4; i++)
#pragma unroll
                for (int j = 0; j < 4; j++)
                    acc[i][j] += av[i] * bv[j];
        }
        __syncthreads();
    }

    const int row0 = bm + ty * 4, col0 = bn + tx * 4;
#pragma unroll
    for (int i = 0; i < 4; i++) {
        int r = row0 + i;
#pragma unroll
        for (int j = 0; j < 4; j++) {
            int c = col0 + j;
            float vv = acc[i][j];
            if (EPI == 0) {
                out[(size_t)r * N + c] = vv;
            } else if (EPI == 1) {
                out[(size_t)r * N + c] = vv + bias[c] + res[(size_t)r * N + c];
            } else if (EPI == 2) {
                out[(size_t)r * N + c] = fmaxf(vv + bias[c], 0.f);
            } else {
                int hh = c & 7, hd = c >> 3;
                int bb = r >> 11, ss = r & (SS - 1);
                out[(((size_t)(bb * HH + hh) * SS) + ss) * HDIM + hd] = vv;
            }
        }
    }
}

// ---------------- attention: softmax(QK^T/4) V, per (b,h), head layout --------
// grid (S/64, H, B), 64 threads; one query per thread; no max-subtraction
// (scores bounded; exp never overflows fp32; analytically identical softmax).
__global__ void __launch_bounds__(64) attn_kernel(
    const float* __restrict__ q, const float* __restrict__ k,
    const float* __restrict__ v, float* __restrict__ out)
{
    __shared__ __align__(16) unsigned long long Ks[128 * 8];
    __shared__ __align__(16) unsigned long long Vs[128 * 8];
    const int tid = threadIdx.x;
    const int h = blockIdx.y, b = blockIdx.z;
    const int qi = blockIdx.x * 64 + tid;
    const size_t head = (size_t)(b * HH + h) * SS;

    // Load this thread's query row (16 floats) as 8 packed pairs
    const float* qr = q + (head + qi) * HDIM;
    unsigned long long qp[8];
#pragma unroll
    for (int i = 0; i < 4; i++) {
        float4 t = ((const float4*)qr)[i];
        qp[2 * i]     = pack2(t.x, t.y);
        qp[2 * i + 1] = pack2(t.z, t.w);
    }

    const unsigned long long z2 = pack2(0.f, 0.f);
    unsigned long long acc[8];
#pragma unroll
    for (int i = 0; i < 8; i++) acc[i] = z2;
    float l = 0.f;

    const float4* kb = (const float4*)(k + head * HDIM);
    const float4* vb = (const float4*)(v + head * HDIM);

    for (int kt = 0; kt < SS / 128; kt++) {
        __syncthreads();
        const float4* ksrc = kb + kt * 128 * 4;
        const float4* vsrc = vb + kt * 128 * 4;
        float4* kdst = (float4*)Ks;
        float4* vdst = (float4*)Vs;
#pragma unroll
        for (int i = 0; i < 8; i++) {
            kdst[tid + i * 64] = ksrc[tid + i * 64];
            vdst[tid + i * 64] = vsrc[tid + i * 64];
        }
        __syncthreads();

#pragma unroll 4
        for (int kk = 0; kk < 128; kk++) {
            const ulonglong2* kr = (const ulonglong2*)(Ks + kk * 8);
            ulonglong2 k0 = kr[0], k1 = kr[1], k2 = kr[2], k3 = kr[3];
            // two independent chains for ILP
            unsigned long long s0 = fma2(qp[0], k0.x, z2);
            unsigned long long s1 = fma2(qp[1], k0.y, z2);
            s0 = fma2(qp[2], k1.x, s0);
            s1 = fma2(qp[3], k1.y, s1);
            s0 = fma2(qp[4], k2.x, s0);
            s1 = fma2(qp[5], k2.y, s1);
            s0 = fma2(qp[6], k3.x, s0);
            s1 = fma2(qp[7], k3.y, s1);
            float a0, a1, b0, b1;
            unpack2(s0, a0, a1);
            unpack2(s1, b0, b1);
            float s = (a0 + a1) + (b0 + b1);
            float p = __expf(s * 0.25f);   // /sqrt(HD=16)
            l += p;
            unsigned long long p2 = pack2(p, p);
            const ulonglong2* vr = (const ulonglong2*)(Vs + kk * 8);
            ulonglong2 v0 = vr[0], v1 = vr[1], v2 = vr[2], v3 = vr[3];
            acc[0] = fma2(p2, v0.x, acc[0]);
            acc[1] = fma2(p2, v0.y, acc[1]);
            acc[2] = fma2(p2, v1.x, acc[2]);
            acc[3] = fma2(p2, v1.y, acc[3]);
            acc[4] = fma2(p2, v2.x, acc[4]);
            acc[5] = fma2(p2, v2.y, acc[5]);
            acc[6] = fma2(p2, v3.x, acc[6]);
            acc[7] = fma2(p2, v3.y, acc[7]);
        }
    }

    // write to (B,S,D) layout: col = hd*8 + h   (the reference's interleaved merge)
    float inv = 1.0f / l;
    float* ob = out + ((size_t)(b * SS) + qi) * DD + h;
#pragma unroll
    for (int i = 0; i < 8; i++) {
        float lo, hi;
        unpack2(acc[i], lo, hi);
        ob[(2 * i) * HH]     = lo * inv;
        ob[(2 * i + 1) * HH] = hi * inv;
    }
}

// ---------------- custom "layernorm": c / var, var unbiased (N-1) -------------
__global__ void __launch_bounds__(256) ln_kernel(const float* __restrict__ x,
                                                 float* __restrict__ y)
{
    int row  = blockIdx.x * 8 + (threadIdx.x >> 5);
    int lane = threadIdx.x & 31;
    float4 t = ((const float4*)(x + (size_t)row * DD))[lane];
    float s = t.x + t.y + t.z + t.w;
#pragma unroll
    for (int o = 16; o; o >>= 1) s += __shfl_xor_sync(~0u, s, o);
    float m = s * (1.0f / DD);
    float cx = t.x - m, cy = t.y - m, cz = t.z - m, cw = t.w - m;
    float ss = cx * cx + cy * cy + cz * cz + cw * cw;
#pragma unroll
    for (int o = 16; o; o >>= 1) ss += __shfl_xor_sync(~0u, ss, o);
    float inv = (float)(DD - 1) / ss;   // 1/var with unbiased var
    float4 o4 = {cx * inv, cy * inv, cz * inv, cw * inv};
    ((float4*)(y + (size_t)row * DD))[lane] = o4;
}

// ---------------- launch --------------------------------------------------------
extern "C" void kernel_launch(void* const* d_in, const int* in_sizes, int n_in,
                              void* d_out, int out_size) {
    (void)in_sizes; (void)n_in; (void)out_size;
    const float* x_tgt = (const float*)d_in[0];
    const float* enc   = (const float*)d_in[1];
    const float* swq   = (const float*)d_in[2];
    const float* swk   = (const float*)d_in[3];
    const float* swv   = (const float*)d_in[4];
    const float* cwq   = (const float*)d_in[5];
    const float* cwk   = (const float*)d_in[6];
    const float* cwv   = (const float*)d_in[7];
    const float* w1    = (const float*)d_in[8];
    const float* b1    = (const float*)d_in[9];
    const float* w2    = (const float*)d_in[10];
    const float* b2    = (const float*)d_in[11];
    const float* w3    = (const float*)d_in[12];
    const float* b3    = (const float*)d_in[13];
    const float* w4    = (const float*)d_in[14];
    const float* b4    = (const float*)d_in[15];
    float* out = (float*)d_out;

    float *q, *k, *v, *attn, *r1, *r2, *ln, *h;
    cudaGetSymbolAddress((void**)&q,    g_q);
    cudaGetSymbolAddress((void**)&k,    g_k);
    cudaGetSymbolAddress((void**)&v,    g_v);
    cudaGetSymbolAddress((void**)&attn, g_attn);
    cudaGetSymbolAddress((void**)&r1,   g_r1);
    cudaGetSymbolAddress((void**)&r2,   g_r2);
    cudaGetSymbolAddress((void**)&ln,   g_ln);
    cudaGetSymbolAddress((void**)&h,    g_h);

    const dim3 gD(2, MROWS / 64);      // N=128 GEMMs
    const dim3 gF(8, MROWS / 64);      // N=512 GEMM
    const dim3 gA(SS / 64, HH, BB);    // attention

    // ---- self attention: Q,K,V all from x_tgt ----
    gemm_kernel<128, 128, 3><<<gD, 256>>>(x_tgt, swq, nullptr, nullptr, q);
    gemm_kernel<128, 128, 3><<<gD, 256>>>(x_tgt, swk, nullptr, nullptr, k);
    gemm_kernel<128, 128, 3><<<gD, 256>>>(x_tgt, swv, nullptr, nullptr, v);
    attn_kernel<<<gA, 64>>>(q, k, v, attn);
    // r1 = sa@w1 + b1 + x_tgt
    gemm_kernel<128, 128, 1><<<gD, 256>>>(attn, w1, b1, x_tgt, r1);

    // ---- "cross" attention (faithful quirk): Q from enc_out, K/V from x_tgt ----
    gemm_kernel<128, 128, 3><<<gD, 256>>>(enc,   cwq, nullptr, nullptr, q);
    gemm_kernel<128, 128, 3><<<gD, 256>>>(x_tgt, cwk, nullptr, nullptr, k);
    gemm_kernel<128, 128, 3><<<gD, 256>>>(x_tgt, cwv, nullptr, nullptr, v);
    attn_kernel<<<gA, 64>>>(q, k, v, attn);
    // r2 = ca@w2 + b2 + r1
    gemm_kernel<128, 128, 1><<<gD, 256>>>(attn, w2, b2, r1, r2);

    // ---- norm + FFN ----
    ln_kernel<<<MROWS / 8, 256>>>(r2, ln);
    gemm_kernel<128, 512, 2><<<gF, 256>>>(ln, w3, b3, nullptr, h);   // relu
    gemm_kernel<512, 128, 1><<<gD, 256>>>(h, w4, b4, r2, out);
}

// round 2
// speedup vs baseline: 1.1429x; 1.1429x over previous
#include <cuda_runtime.h>
#include <cuda_bf16.h>

// Problem constants
#define BB 2
#define SS 2048
#define DD 128
#define HH 8
#define HDIM 16
#define DFF 512
#define MROWS (BB*SS)     // 4096
#define BHS  (BB*HH*SS)   // 32768
#define SPLITS 4
#define KEYS_PER_SPLIT (SS / SPLITS)   // 512

// ---------------- scratch (device globals; no allocation allowed) -------------
__device__ float g_q[BB*HH*SS*HDIM];
__device__ float g_k[BB*HH*SS*HDIM];
__device__ float g_v[BB*HH*SS*HDIM];
__device__ float g_attn[BB*SS*DD];
__device__ float g_r1[BB*SS*DD];
__device__ float g_r2[BB*SS*DD];
__device__ float g_ln[BB*SS*DD];
__device__ float g_h[BB*SS*DFF];
__device__ float g_pacc[SPLITS * BHS * HDIM];   // 8.4 MB partial PV accumulators
__device__ float g_pl[SPLITS * BHS];            // partial softmax denominators

// ---------------- packed f32x2 helpers (B300 2x fp32 path) --------------------
typedef unsigned long long u64;
__device__ __forceinline__ u64 pack2(float lo, float hi) {
    u64 r;
    asm("mov.b64 %0, {%1, %2};" : "=l"(r)
        : "r"(__float_as_uint(lo)), "r"(__float_as_uint(hi)));
    return r;
}
__device__ __forceinline__ void unpack2(u64 p, float& lo, float& hi) {
    unsigned int a, b;
    asm("mov.b64 {%0, %1}, %2;" : "=r"(a), "=r"(b) : "l"(p));
    lo = __uint_as_float(a); hi = __uint_as_float(b);
}
__device__ __forceinline__ u64 fma2(u64 a, u64 b, u64 c) {
    u64 d;
    asm("fma.rn.f32x2 %0, %1, %2, %3;" : "=l"(d) : "l"(a), "l"(b), "l"(c));
    return d;
}

// ---------------- generic tiled GEMM:  out = A(MxK) @ W(KxN) + epilogue -------
// EPI: 0 = plain store
//      1 = + bias[c] + res[r*N+c]
//      2 = relu(+ bias[c])
template<int K, int N, int EPI>
__global__ void __launch_bounds__(256) gemm_kernel(
    const float* __restrict__ A, const float* __restrict__ W,
    const float* __restrict__ bias, const float* __restrict__ res,
    float* __restrict__ out)
{
    __shared__ float As[32][64];
    __shared__ float Ws[32][64];
    const int tid = threadIdx.x;
    const int tx = tid & 15, ty = tid >> 4;
    const int bm = blockIdx.y * 64, bn = blockIdx.x * 64;

    float acc[4][4] = {};

    for (int kt = 0; kt < K; kt += 32) {
#pragma unroll
        for (int i = 0; i < 2; i++) {
            int idx = tid * 2 + i;
            int row = idx >> 3;
            int kc  = (idx & 7) * 4;
            float4 t = *(const float4*)&A[(size_t)(bm + row) * K + kt + kc];
            As[kc + 0][row] = t.x; As[kc + 1][row] = t.y;
            As[kc + 2][row] = t.z; As[kc + 3][row] = t.w;
        }
#pragma unroll
        for (int i = 0; i < 2; i++) {
            int idx = tid * 2 + i;
            int r = idx >> 4;
            int c = (idx & 15) * 4;
            *(float4*)&Ws[r][c] = *(const float4*)&W[(size_t)(kt + r) * N + bn + c];
        }
        __syncthreads();
#pragma unroll
        for (int kk = 0; kk < 32; kk++) {
            float4 a4 = *(const float4*)&As[kk][ty * 4];
            float4 b4 = *(const float4*)&Ws[kk][tx * 4];
            float av[4] = {a4.x, a4.y, a4.z, a4.w};
            float bv[4] = {b4.x, b4.y, b4.z, b4.w};
#pragma unroll
            for (int i = 0; i < 4; i++)
#pragma unroll
                for (int j = 0; j < 4; j++)
                    acc[i][j] += av[i] * bv[j];
        }
        __syncthreads();
    }

    const int row0 = bm + ty * 4, col0 = bn + tx * 4;
#pragma unroll
    for (int i = 0; i < 4; i++) {
        int r = row0 + i;
#pragma unroll
        for (int j = 0; j < 4; j++) {
            int c = col0 + j;
            float vv = acc[i][j];
            if (EPI == 0) {
                out[(size_t)r * N + c] = vv;
            } else if (EPI == 1) {
                out[(size_t)r * N + c] = vv + bias[c] + res[(size_t)r * N + c];
            } else {
                out[(size_t)r * N + c] = fmaxf(vv + bias[c], 0.f);
            }
        }
    }
}

// ---------------- fused QKV projection, scatter to head layout ----------------
// grid (6, MROWS/64): blockIdx.x>>1 selects {Q,K,V}; Q may use a different A
// (cross-attn quirk: Q from enc_out, K/V from x_tgt). Scatter col c -> h=c&7,
// hd=c>>3 into [b][h][s][hd].
__global__ void __launch_bounds__(256) gemm_qkv_kernel(
    const float* __restrict__ Aq, const float* __restrict__ Akv,
    const float* __restrict__ wq, const float* __restrict__ wk,
    const float* __restrict__ wv,
    float* __restrict__ qo, float* __restrict__ ko, float* __restrict__ vo)
{
    const int which = blockIdx.x >> 1;
    const float* A = (which == 0) ? Aq : Akv;
    const float* W = (which == 0) ? wq : ((which == 1) ? wk : wv);
    float* out     = (which == 0) ? qo : ((which == 1) ? ko : vo);

    __shared__ float As[32][64];
    __shared__ float Ws[32][64];
    const int tid = threadIdx.x;
    const int tx = tid & 15, ty = tid >> 4;
    const int bm = blockIdx.y * 64, bn = (blockIdx.x & 1) * 64;

    float acc[4][4] = {};

    for (int kt = 0; kt < DD; kt += 32) {
#pragma unroll
        for (int i = 0; i < 2; i++) {
            int idx = tid * 2 + i;
            int row = idx >> 3;
            int kc  = (idx & 7) * 4;
            float4 t = *(const float4*)&A[(size_t)(bm + row) * DD + kt + kc];
            As[kc + 0][row] = t.x; As[kc + 1][row] = t.y;
            As[kc + 2][row] = t.z; As[kc + 3][row] = t.w;
        }
#pragma unroll
        for (int i = 0; i < 2; i++) {
            int idx = tid * 2 + i;
            int r = idx >> 4;
            int c = (idx & 15) * 4;
            *(float4*)&Ws[r][c] = *(const float4*)&W[(size_t)(kt + r) * DD + bn + c];
        }
        __syncthreads();
#pragma unroll
        for (int kk = 0; kk < 32; kk++) {
            float4 a4 = *(const float4*)&As[kk][ty * 4];
            float4 b4 = *(const float4*)&Ws[kk][tx * 4];
            float av[4] = {a4.x, a4.y, a4.z, a4.w};
            float bv[4] = {b4.x, b4.y, b4.z, b4.w};
#pragma unroll
            for (int i = 0; i < 4; i++)
#pragma unroll
                for (int j = 0; j < 4; j++)
                    acc[i][j] += av[i] * bv[j];
        }
        __syncthreads();
    }

    const int row0 = bm + ty * 4, col0 = bn + tx * 4;
#pragma unroll
    for (int i = 0; i < 4; i++) {
        int r = row0 + i;
        int bb = r >> 11, ss = r & (SS - 1);
#pragma unroll
        for (int j = 0; j < 4; j++) {
            int c = col0 + j;
            int hh = c & 7, hd = c >> 3;
            out[(((size_t)(bb * HH + hh) * SS) + ss) * HDIM + hd] = acc[i][j];
        }
    }
}

// ---------------- attention, split-KV partials --------------------------------
// grid (S/256, SPLITS, B*H), 128 threads, 2 queries/thread.
// Q rows pre-scaled by 0.25*log2(e), so p = exp2(q'.k) = exp(q.k/sqrt(16)).
// No max-subtraction (scores bounded, fp32 exp safe) => partials combine by sum.
__global__ void __launch_bounds__(128) attn_part_kernel(
    const float* __restrict__ q, const float* __restrict__ k,
    const float* __restrict__ v,
    float* __restrict__ pacc, float* __restrict__ pl)
{
    __shared__ __align__(16) u64 Ks[128 * 8];
    __shared__ __align__(16) u64 Vs[128 * 8];
    const int tid = threadIdx.x;
    const int bh = blockIdx.z;
    const int split = blockIdx.y;
    const int q0 = blockIdx.x * 256 + tid;
    const int q1 = q0 + 128;
    const size_t head = (size_t)bh * SS;
    const float sc = 0.25f * 1.4426950408889634f;

    u64 qa[8], qb[8];
    {
        const float4* qr = (const float4*)(q + (head + q0) * HDIM);
#pragma unroll
        for (int i = 0; i < 4; i++) {
            float4 t = qr[i];
            qa[2 * i]     = pack2(t.x * sc, t.y * sc);
            qa[2 * i + 1] = pack2(t.z * sc, t.w * sc);
        }
        qr = (const float4*)(q + (head + q1) * HDIM);
#pragma unroll
        for (int i = 0; i < 4; i++) {
            float4 t = qr[i];
            qb[2 * i]     = pack2(t.x * sc, t.y * sc);
            qb[2 * i + 1] = pack2(t.z * sc, t.w * sc);
        }
    }

    const u64 z2 = pack2(0.f, 0.f);
    u64 acca[8], accb[8];
#pragma unroll
    for (int i = 0; i < 8; i++) { acca[i] = z2; accb[i] = z2; }
    float la = 0.f, lb = 0.f;

    const int key0 = split * KEYS_PER_SPLIT;
    const float4* kb4 = (const float4*)(k + (head + key0) * HDIM);
    const float4* vb4 = (const float4*)(v + (head + key0) * HDIM);

    for (int kt = 0; kt < KEYS_PER_SPLIT / 128; kt++) {
        __syncthreads();
        const float4* ksrc = kb4 + kt * 128 * 4;
        const float4* vsrc = vb4 + kt * 128 * 4;
        float4* kdst = (float4*)Ks;
        float4* vdst = (float4*)Vs;
#pragma unroll
        for (int i = 0; i < 4; i++) {
            kdst[tid + i * 128] = ksrc[tid + i * 128];
            vdst[tid + i * 128] = vsrc[tid + i * 128];
        }
        __syncthreads();

#pragma unroll 2
        for (int kk = 0; kk < 128; kk++) {
            const ulonglong2* kr = (const ulonglong2*)(Ks + kk * 8);
            ulonglong2 k0 = kr[0], k1 = kr[1], k2 = kr[2], k3 = kr[3];
            // 4 independent fma2 chains (2 per query) for ILP
            u64 a0 = fma2(qa[0], k0.x, z2);
            u64 a1 = fma2(qa[1], k0.y, z2);
            u64 b0 = fma2(qb[0], k0.x, z2);
            u64 b1 = fma2(qb[1], k0.y, z2);
            a0 = fma2(qa[2], k1.x, a0);  a1 = fma2(qa[3], k1.y, a1);
            b0 = fma2(qb[2], k1.x, b0);  b1 = fma2(qb[3], k1.y, b1);
            a0 = fma2(qa[4], k2.x, a0);  a1 = fma2(qa[5], k2.y, a1);
            b0 = fma2(qb[4], k2.x, b0);  b1 = fma2(qb[5], k2.y, b1);
            a0 = fma2(qa[6], k3.x, a0);  a1 = fma2(qa[7], k3.y, a1);
            b0 = fma2(qb[6], k3.x, b0);  b1 = fma2(qb[7], k3.y, b1);
            float x0, x1, x2, x3, y0, y1, y2, y3;
            unpack2(a0, x0, x1); unpack2(a1, x2, x3);
            unpack2(b0, y0, y1); unpack2(b1, y2, y3);
            float pa = exp2f((x0 + x1) + (x2 + x3));
            float pb = exp2f((y0 + y1) + (y2 + y3));
            la += pa; lb += pb;
            u64 pa2 = pack2(pa, pa);
            u64 pb2 = pack2(pb, pb);
            const ulonglong2* vr = (const ulonglong2*)(Vs + kk * 8);
            ulonglong2 v0 = vr[0], v1 = vr[1], v2 = vr[2], v3 = vr[3];
            acca[0] = fma2(pa2, v0.x, acca[0]);  accb[0] = fma2(pb2, v0.x, accb[0]);
            acca[1] = fma2(pa2, v0.y, acca[1]);  accb[1] = fma2(pb2, v0.y, accb[1]);
            acca[2] = fma2(pa2, v1.x, acca[2]);  accb[2] = fma2(pb2, v1.x, accb[2]);
            acca[3] = fma2(pa2, v1.y, acca[3]);  accb[3] = fma2(pb2, v1.y, accb[3]);
            acca[4] = fma2(pa2, v2.x, acca[4]);  accb[4] = fma2(pb2, v2.x, accb[4]);
            acca[5] = fma2(pa2, v2.y, acca[5]);  accb[5] = fma2(pb2, v2.y, accb[5]);
            acca[6] = fma2(pa2, v3.x, acca[6]);  accb[6] = fma2(pb2, v3.x, accb[6]);
            acca[7] = fma2(pa2, v3.y, acca[7]);  accb[7] = fma2(pb2, v3.y, accb[7]);
        }
    }

    // store partials: [split][bh*S + q][16] and [split][bh*S + q]
    {
        float o[16];
#pragma unroll
        for (int i = 0; i < 8; i++) unpack2(acca[i], o[2 * i], o[2 * i + 1]);
        float4* dst = (float4*)(pacc + ((size_t)split * BHS + head + q0) * HDIM);
#pragma unroll
        for (int i = 0; i < 4; i++) dst[i] = ((float4*)o)[i];
        pl[(size_t)split * BHS + head + q0] = la;

#pragma unroll
        for (int i = 0; i < 8; i++) unpack2(accb[i], o[2 * i], o[2 * i + 1]);
        dst = (float4*)(pacc + ((size_t)split * BHS + head + q1) * HDIM);
#pragma unroll
        for (int i = 0; i < 4; i++) dst[i] = ((float4*)o)[i];
        pl[(size_t)split * BHS + head + q1] = lb;
    }
}

// ---------------- combine partials, normalize, scatter to (B,S,D) -------------
// col = hd*8 + h  (the reference's interleaved merge)
__global__ void __launch_bounds__(256) attn_combine_kernel(
    const float* __restrict__ pacc, const float* __restrict__ pl,
    float* __restrict__ out)
{
    const int idx = blockIdx.x * 256 + threadIdx.x;   // bh*S + s
    float4 s0 = {0, 0, 0, 0}, s1 = s0, s2 = s0, s3 = s0;
    float l = 0.f;
#pragma unroll
    for (int sp = 0; sp < SPLITS; sp++) {
        const float4* p = (const float4*)(pacc + ((size_t)sp * BHS + idx) * HDIM);
        float4 t0 = p[0], t1 = p[1], t2 = p[2], t3 = p[3];
        s0.x += t0.x; s0.y += t0.y; s0.z += t0.z; s0.w += t0.w;
        s1.x += t1.x; s1.y += t1.y; s1.z += t1.z; s1.w += t1.w;
        s2.x += t2.x; s2.y += t2.y; s2.z += t2.z; s2.w += t2.w;
        s3.x += t3.x; s3.y += t3.y; s3.z += t3.z; s3.w += t3.w;
        l += pl[(size_t)sp * BHS + idx];
    }
    float inv = 1.0f / l;
    const int bh = idx >> 11;          // / S
    const int b = bh >> 3, h = bh & 7;
    const int s = idx & (SS - 1);
    float* ob = out + ((size_t)(b * SS) + s) * DD + h;
    float vals[16] = {s0.x, s0.y, s0.z, s0.w, s1.x, s1.y, s1.z, s1.w,
                      s2.x, s2.y, s2.z, s2.w, s3.x, s3.y, s3.z, s3.w};
#pragma unroll
    for (int hd = 0; hd < 16; hd++) ob[hd * HH] = vals[hd] * inv;
}

// ---------------- custom "layernorm": c / var, var unbiased (N-1) -------------
__global__ void __launch_bounds__(256) ln_kernel(const float* __restrict__ x,
                                                 float* __restrict__ y)
{
    int row  = blockIdx.x * 8 + (threadIdx.x >> 5);
    int lane = threadIdx.x & 31;
    float4 t = ((const float4*)(x + (size_t)row * DD))[lane];
    float s = t.x + t.y + t.z + t.w;
#pragma unroll
    for (int o = 16; o; o >>= 1) s += __shfl_xor_sync(~0u, s, o);
    float m = s * (1.0f / DD);
    float cx = t.x - m, cy = t.y - m, cz = t.z - m, cw = t.w - m;
    float ss = cx * cx + cy * cy + cz * cz + cw * cw;
#pragma unroll
    for (int o = 16; o; o >>= 1) ss += __shfl_xor_sync(~0u, ss, o);
    float inv = (float)(DD - 1) / ss;
    float4 o4 = {cx * inv, cy * inv, cz * inv, cw * inv};
    ((float4*)(y + (size_t)row * DD))[lane] = o4;
}

// ---------------- launch --------------------------------------------------------
extern "C" void kernel_launch(void* const* d_in, const int* in_sizes, int n_in,
                              void* d_out, int out_size) {
    (void)in_sizes; (void)n_in; (void)out_size;
    const float* x_tgt = (const float*)d_in[0];
    const float* enc   = (const float*)d_in[1];
    const float* swq   = (const float*)d_in[2];
    const float* swk   = (const float*)d_in[3];
    const float* swv   = (const float*)d_in[4];
    const float* cwq   = (const float*)d_in[5];
    const float* cwk   = (const float*)d_in[6];
    const float* cwv   = (const float*)d_in[7];
    const float* w1    = (const float*)d_in[8];
    const float* b1    = (const float*)d_in[9];
    const float* w2    = (const float*)d_in[10];
    const float* b2    = (const float*)d_in[11];
    const float* w3    = (const float*)d_in[12];
    const float* b3    = (const float*)d_in[13];
    const float* w4    = (const float*)d_in[14];
    const float* b4    = (const float*)d_in[15];
    float* out = (float*)d_out;

    float *q, *k, *v, *attn, *r1, *r2, *ln, *h, *pacc, *pl;
    cudaGetSymbolAddress((void**)&q,    g_q);
    cudaGetSymbolAddress((void**)&k,    g_k);
    cudaGetSymbolAddress((void**)&v,    g_v);
    cudaGetSymbolAddress((void**)&attn, g_attn);
    cudaGetSymbolAddress((void**)&r1,   g_r1);
    cudaGetSymbolAddress((void**)&r2,   g_r2);
    cudaGetSymbolAddress((void**)&ln,   g_ln);
    cudaGetSymbolAddress((void**)&h,    g_h);
    cudaGetSymbolAddress((void**)&pacc, g_pacc);
    cudaGetSymbolAddress((void**)&pl,   g_pl);

    const dim3 gD(2, MROWS / 64);                 // N=128 GEMMs
    const dim3 gF(8, MROWS / 64);                 // N=512 GEMM
    const dim3 gQKV(6, MROWS / 64);               // fused QKV
    const dim3 gA(SS / 256, SPLITS, BB * HH);     // attention partials
    const dim3 gC(BHS / 256);                     // combine

    // ---- self attention: Q,K,V all from x_tgt ----
    gemm_qkv_kernel<<<gQKV, 256>>>(x_tgt, x_tgt, swq, swk, swv, q, k, v);
    attn_part_kernel<<<gA, 128>>>(q, k, v, pacc, pl);
    attn_combine_kernel<<<gC, 256>>>(pacc, pl, attn);
    gemm_kernel<128, 128, 1><<<gD, 256>>>(attn, w1, b1, x_tgt, r1);

    // ---- "cross" attention (faithful quirk): Q from enc_out, K/V from x_tgt ----
    gemm_qkv_kernel<<<gQKV, 256>>>(enc, x_tgt, cwq, cwk, cwv, q, k, v);
    attn_part_kernel<<<gA, 128>>>(q, k, v, pacc, pl);
    attn_combine_kernel<<<gC, 256>>>(pacc, pl, attn);
    gemm_kernel<128, 128, 1><<<gD, 256>>>(attn, w2, b2, r1, r2);

    // ---- norm + FFN ----
    ln_kernel<<<MROWS / 8, 256>>>(r2, ln);
    gemm_kernel<128, 512, 2><<<gF, 256>>>(ln, w3, b3, nullptr, h);   // relu
    gemm_kernel<512, 128, 1><<<gD, 256>>>(h, w4, b4, r2, out);
}

// round 3
// speedup vs baseline: 2.3164x; 2.0268x over previous
#include <cuda_runtime.h>
#include <cuda_bf16.h>

// Problem constants
#define BB 2
#define SS 2048
#define DD 128
#define HH 8
#define HDIM 16
#define DFF 512
#define MROWS (BB*SS)     // 4096
#define BHS  (BB*HH*SS)   // 32768

// ---------------- scratch (device globals; no allocation allowed) -------------
__device__ float g_q[BB*HH*SS*HDIM];
__device__ float g_k[BB*HH*SS*HDIM];
__device__ float g_v[BB*HH*SS*HDIM];
__device__ float g_attn[BB*SS*DD];
__device__ float g_r1[BB*SS*DD];
__device__ float g_r2[BB*SS*DD];
__device__ float g_ln[BB*SS*DD];
__device__ float g_h[BB*SS*DFF];

// ---------------- helpers -----------------------------------------------------
__device__ __forceinline__ unsigned pack_bf16x2(float lo, float hi) {
    unsigned r;
    asm("cvt.rn.bf16x2.f32 %0, %1, %2;" : "=r"(r) : "f"(hi), "f"(lo));
    return r;  // low half = lo, high half = hi
}
__device__ __forceinline__ float ex2(float x) {
    float y;
    asm("ex2.approx.ftz.f32 %0, %1;" : "=f"(y) : "f"(x));
    return y;
}
__device__ __forceinline__ void mma_bf16(
    float& c0, float& c1, float& c2, float& c3,
    unsigned a0, unsigned a1, unsigned a2, unsigned a3,
    unsigned b0, unsigned b1)
{
    asm("mma.sync.aligned.m16n8k16.row.col.f32.bf16.bf16.f32 "
        "{%0,%1,%2,%3},{%4,%5,%6,%7},{%8,%9},{%0,%1,%2,%3};"
        : "+f"(c0), "+f"(c1), "+f"(c2), "+f"(c3)
        : "r"(a0), "r"(a1), "r"(a2), "r"(a3), "r"(b0), "r"(b1));
}

// ---------------- generic tiled GEMM (32x64 tile, 128 thr) --------------------
// out = A(MxK) @ W(KxN) + epilogue
// EPI: 0 plain  1 +bias+res  2 relu(+bias)
template<int K, int N, int EPI>
__global__ void __launch_bounds__(128) gemm_kernel(
    const float* __restrict__ A, const float* __restrict__ W,
    const float* __restrict__ bias, const float* __restrict__ res,
    float* __restrict__ out)
{
    __shared__ float As[32][32];
    __shared__ float Ws[32][64];
    const int tid = threadIdx.x;
    const int tx = tid & 15, ty = tid >> 4;      // 16 x 8
    const int bm = blockIdx.y * 32, bn = blockIdx.x * 64;

    float acc[4][4] = {};

    for (int kt = 0; kt < K; kt += 32) {
#pragma unroll
        for (int i = 0; i < 2; i++) {
            int idx = tid * 2 + i;               // 0..255
            int row = idx >> 3;                  // 0..31
            int kc  = (idx & 7) * 4;
            float4 t = *(const float4*)&A[(size_t)(bm + row) * K + kt + kc];
            As[kc + 0][row] = t.x; As[kc + 1][row] = t.y;
            As[kc + 2][row] = t.z; As[kc + 3][row] = t.w;
        }
#pragma unroll
        for (int i = 0; i < 4; i++) {
            int idx = tid * 4 + i;               // 0..511
            int r = idx >> 4;                    // 0..31
            int cw = (idx & 15) * 4;
            *(float4*)&Ws[r][cw] = *(const float4*)&W[(size_t)(kt + r) * N + bn + cw];
        }
        __syncthreads();
#pragma unroll
        for (int kk = 0; kk < 32; kk++) {
            float4 a4 = *(const float4*)&As[kk][ty * 4];
            float4 b4 = *(const float4*)&Ws[kk][tx * 4];
            float av[4] = {a4.x, a4.y, a4.z, a4.w};
            float bv[4] = {b4.x, b4.y, b4.z, b4.w};
#pragma unroll
            for (int i = 0; i < 4; i++)
#pragma unroll
                for (int j = 0; j < 4; j++)
                    acc[i][j] += av[i] * bv[j];
        }
        __syncthreads();
    }

    const int row0 = bm + ty * 4, col0 = bn + tx * 4;
#pragma unroll
    for (int i = 0; i < 4; i++) {
        int r = row0 + i;
#pragma unroll
        for (int j = 0; j < 4; j++) {
            int c = col0 + j;
            float vv = acc[i][j];
            if (EPI == 0) {
                out[(size_t)r * N + c] = vv;
            } else if (EPI == 1) {
                out[(size_t)r * N + c] = vv + bias[c] + res[(size_t)r * N + c];
            } else {
                out[(size_t)r * N + c] = fmaxf(vv + bias[c], 0.f);
            }
        }
    }
}

// ---------------- fused QKV projection, scatter to head layout ----------------
// grid (6, MROWS/64): blockIdx.x>>1 selects {Q,K,V}; Q may use a different A
// (cross-attn quirk). Scatter col c -> h=c&7, hd=c>>3 into [b][h][s][hd].
__global__ void __launch_bounds__(256) gemm_qkv_kernel(
    const float* __restrict__ Aq, const float* __restrict__ Akv,
    const float* __restrict__ wq, const float* __restrict__ wk,
    const float* __restrict__ wv,
    float* __restrict__ qo, float* __restrict__ ko, float* __restrict__ vo)
{
    const int which = blockIdx.x >> 1;
    const float* A = (which == 0) ? Aq : Akv;
    const float* W = (which == 0) ? wq : ((which == 1) ? wk : wv);
    float* out     = (which == 0) ? qo : ((which == 1) ? ko : vo);

    __shared__ float As[32][64];
    __shared__ float Ws[32][64];
    const int tid = threadIdx.x;
    const int tx = tid & 15, ty = tid >> 4;
    const int bm = blockIdx.y * 64, bn = (blockIdx.x & 1) * 64;

    float acc[4][4] = {};

    for (int kt = 0; kt < DD; kt += 32) {
#pragma unroll
        for (int i = 0; i < 2; i++) {
            int idx = tid * 2 + i;
            int row = idx >> 3;
            int kc  = (idx & 7) * 4;
            float4 t = *(const float4*)&A[(size_t)(bm + row) * DD + kt + kc];
            As[kc + 0][row] = t.x; As[kc + 1][row] = t.y;
            As[kc + 2][row] = t.z; As[kc + 3][row] = t.w;
        }
#pragma unroll
        for (int i = 0; i < 2; i++) {
            int idx = tid * 2 + i;
            int r = idx >> 4;
            int c = (idx & 15) * 4;
            *(float4*)&Ws[r][c] = *(const float4*)&W[(size_t)(kt + r) * DD + bn + c];
        }
        __syncthreads();
#pragma unroll
        for (int kk = 0; kk < 32; kk++) {
            float4 a4 = *(const float4*)&As[kk][ty * 4];
            float4 b4 = *(const float4*)&Ws[kk][tx * 4];
            float av[4] = {a4.x, a4.y, a4.z, a4.w};
            float bv[4] = {b4.x, b4.y, b4.z, b4.w};
#pragma unroll
            for (int i = 0; i < 4; i++)
#pragma unroll
                for (int j = 0; j < 4; j++)
                    acc[i][j] += av[i] * bv[j];
        }
        __syncthreads();
    }

    const int row0 = bm + ty * 4, col0 = bn + tx * 4;
#pragma unroll
    for (int i = 0; i < 4; i++) {
        int r = row0 + i;
        int bb = r >> 11, ss = r & (SS - 1);
#pragma unroll
        for (int j = 0; j < 4; j++) {
            int c = col0 + j;
            int hh = c & 7, hd = c >> 3;
            out[(((size_t)(bb * HH + hh) * SS) + ss) * HDIM + hd] = acc[i][j];
        }
    }
}

// ---------------- flash attention with bf16 tensor cores ----------------------
// grid (S/64, B*H), 128 threads (4 warps), each warp owns 16 query rows.
// QK^T: one m16n8k16 mma per 16x8 score tile (HD=16 = full k).
// P packed to bf16 A-fragments in registers (layout identity), PV via mma.
// No max-subtraction (scores bounded); q pre-scaled by 0.25*log2(e).
#define VSTRIDE 136   // Vs row pad: bank = (4*dim + c) -> conflict-free b32 loads

__global__ void __launch_bounds__(128) attn_mma_kernel(
    const float* __restrict__ q, const float* __restrict__ k,
    const float* __restrict__ v, float* __restrict__ out)
{
    __shared__ unsigned Ks[128][8];              // [key][dim-pair] bf16x2
    __shared__ __nv_bfloat16 Vs[16][VSTRIDE];    // [dim][key] transposed, padded
    const int tid = threadIdx.x, w = tid >> 5, lane = tid & 31;
    const int bh = blockIdx.y, b = bh >> 3, h = bh & 7;
    const int g = lane >> 2, c = lane & 3;
    const size_t head = (size_t)bh * SS;
    const int qrow = blockIdx.x * 64 + w * 16;

    // Q fragment (m16n8k16 A): rows g/g+8, cols 2c,2c+1 / +8. Pre-scaled.
    const float sc = 0.25f * 1.4426950408889634f;
    unsigned qa[4];
    {
        const float* r0 = q + (head + qrow + g) * HDIM;
        const float* r1 = r0 + 8 * HDIM;
        float2 t;
        t = *(const float2*)(r0 + 2 * c);     qa[0] = pack_bf16x2(t.x * sc, t.y * sc);
        t = *(const float2*)(r1 + 2 * c);     qa[1] = pack_bf16x2(t.x * sc, t.y * sc);
        t = *(const float2*)(r0 + 2 * c + 8); qa[2] = pack_bf16x2(t.x * sc, t.y * sc);
        t = *(const float2*)(r1 + 2 * c + 8); qa[3] = pack_bf16x2(t.x * sc, t.y * sc);
    }

    float o[8] = {0, 0, 0, 0, 0, 0, 0, 0};
    float l0 = 0.f, l1 = 0.f;

    for (int kt = 0; kt < SS / 128; kt++) {
        __syncthreads();
        const float4* ksrc = (const float4*)(k + (head + kt * 128) * HDIM);
        const float4* vsrc = (const float4*)(v + (head + kt * 128) * HDIM);
#pragma unroll
        for (int i = 0; i < 4; i++) {
            int idx = tid + i * 128;             // 0..511
            int key = idx >> 2, f4 = idx & 3;
            float4 t = ksrc[idx];
            Ks[key][f4 * 2]     = pack_bf16x2(t.x, t.y);
            Ks[key][f4 * 2 + 1] = pack_bf16x2(t.z, t.w);
            float4 u = vsrc[idx];
            Vs[f4 * 4 + 0][key] = __float2bfloat16(u.x);
            Vs[f4 * 4 + 1][key] = __float2bfloat16(u.y);
            Vs[f4 * 4 + 2][key] = __float2bfloat16(u.z);
            Vs[f4 * 4 + 3][key] = __float2bfloat16(u.w);
        }
        __syncthreads();

#pragma unroll
        for (int kc = 0; kc < 8; kc++) {         // 16 keys per iter
            // scores: two 16x8 tiles (keys kc*16+0..7 and +8..15)
            float s0 = 0, s1 = 0, s2 = 0, s3 = 0, s4 = 0, s5 = 0, s6 = 0, s7 = 0;
            {
                unsigned b0 = Ks[kc * 16 + g][c];
                unsigned b1 = Ks[kc * 16 + g][c + 4];
                mma_bf16(s0, s1, s2, s3, qa[0], qa[1], qa[2], qa[3], b0, b1);
                b0 = Ks[kc * 16 + 8 + g][c];
                b1 = Ks[kc * 16 + 8 + g][c + 4];
                mma_bf16(s4, s5, s6, s7, qa[0], qa[1], qa[2], qa[3], b0, b1);
            }
            float p0 = ex2(s0), p1 = ex2(s1), p2 = ex2(s2), p3 = ex2(s3);
            float p4 = ex2(s4), p5 = ex2(s5), p6 = ex2(s6), p7 = ex2(s7);
            l0 += (p0 + p1) + (p4 + p5);         // row g
            l1 += (p2 + p3) + (p6 + p7);         // row g+8
            // P A-fragment for PV (k = keys kc*16..kc*16+15)
            unsigned A0 = pack_bf16x2(p0, p1);   // (g,   keys 2c,2c+1)
            unsigned A1 = pack_bf16x2(p2, p3);   // (g+8, keys 2c,2c+1)
            unsigned A2 = pack_bf16x2(p4, p5);   // (g,   keys 2c+8,+9)
            unsigned A3 = pack_bf16x2(p6, p7);   // (g+8, keys 2c+8,+9)
            // PV: n-tiles dims 0-7 and 8-15; B from transposed Vs
            unsigned vb0 = *(const unsigned*)&Vs[g][kc * 16 + 2 * c];
            unsigned vb1 = *(const unsigned*)&Vs[g][kc * 16 + 2 * c + 8];
            mma_bf16(o[0], o[1], o[2], o[3], A0, A1, A2, A3, vb0, vb1);
            vb0 = *(const unsigned*)&Vs[8 + g][kc * 16 + 2 * c];
            vb1 = *(const unsigned*)&Vs[8 + g][kc * 16 + 2 * c + 8];
            mma_bf16(o[4], o[5], o[6], o[7], A0, A1, A2, A3, vb0, vb1);
        }
    }

    // reduce row denominators over the quad (lanes 4g..4g+3)
    l0 += __shfl_xor_sync(~0u, l0, 1); l0 += __shfl_xor_sync(~0u, l0, 2);
    l1 += __shfl_xor_sync(~0u, l1, 1); l1 += __shfl_xor_sync(~0u, l1, 2);
    const float inv0 = 1.0f / l0, inv1 = 1.0f / l1;

    // write to (B,S,D): col = hd*8 + h  (reference's interleaved merge)
    float* ob0 = out + ((size_t)(b * SS) + qrow + g) * DD + h;
    float* ob1 = out + ((size_t)(b * SS) + qrow + 8 + g) * DD + h;
    ob0[(2 * c) * HH]     = o[0] * inv0;
    ob0[(2 * c + 1) * HH] = o[1] * inv0;
    ob0[(8 + 2 * c) * HH] = o[4] * inv0;
    ob0[(9 + 2 * c) * HH] = o[5] * inv0;
    ob1[(2 * c) * HH]     = o[2] * inv1;
    ob1[(2 * c + 1) * HH] = o[3] * inv1;
    ob1[(8 + 2 * c) * HH] = o[6] * inv1;
    ob1[(9 + 2 * c) * HH] = o[7] * inv1;
}

// ---------------- custom "layernorm": c / var, var unbiased (N-1) -------------
__global__ void __launch_bounds__(256) ln_kernel(const float* __restrict__ x,
                                                 float* __restrict__ y)
{
    int row  = blockIdx.x * 8 + (threadIdx.x >> 5);
    int lane = threadIdx.x & 31;
    float4 t = ((const float4*)(x + (size_t)row * DD))[lane];
    float s = t.x + t.y + t.z + t.w;
#pragma unroll
    for (int o = 16; o; o >>= 1) s += __shfl_xor_sync(~0u, s, o);
    float m = s * (1.0f / DD);
    float cx = t.x - m, cy = t.y - m, cz = t.z - m, cw = t.w - m;
    float ss = cx * cx + cy * cy + cz * cz + cw * cw;
#pragma unroll
    for (int o = 16; o; o >>= 1) ss += __shfl_xor_sync(~0u, ss, o);
    float inv = (float)(DD - 1) / ss;
    float4 o4 = {cx * inv, cy * inv, cz * inv, cw * inv};
    ((float4*)(y + (size_t)row * DD))[lane] = o4;
}

// ---------------- launch --------------------------------------------------------
extern "C" void kernel_launch(void* const* d_in, const int* in_sizes, int n_in,
                              void* d_out, int out_size) {
    (void)in_sizes; (void)n_in; (void)out_size;
    const float* x_tgt = (const float*)d_in[0];
    const float* enc   = (const float*)d_in[1];
    const float* swq   = (const float*)d_in[2];
    const float* swk   = (const float*)d_in[3];
    const float* swv   = (const float*)d_in[4];
    const float* cwq   = (const float*)d_in[5];
    const float* cwk   = (const float*)d_in[6];
    const float* cwv   = (const float*)d_in[7];
    const float* w1    = (const float*)d_in[8];
    const float* b1    = (const float*)d_in[9];
    const float* w2    = (const float*)d_in[10];
    const float* b2    = (const float*)d_in[11];
    const float* w3    = (const float*)d_in[12];
    const float* b3    = (const float*)d_in[13];
    const float* w4    = (const float*)d_in[14];
    const float* b4    = (const float*)d_in[15];
    float* out = (float*)d_out;

    float *q, *k, *v, *attn, *r1, *r2, *ln, *h;
    cudaGetSymbolAddress((void**)&q,    g_q);
    cudaGetSymbolAddress((void**)&k,    g_k);
    cudaGetSymbolAddress((void**)&v,    g_v);
    cudaGetSymbolAddress((void**)&attn, g_attn);
    cudaGetSymbolAddress((void**)&r1,   g_r1);
    cudaGetSymbolAddress((void**)&r2,   g_r2);
    cudaGetSymbolAddress((void**)&ln,   g_ln);
    cudaGetSymbolAddress((void**)&h,    g_h);

    const dim3 gD(2, MROWS / 32);                 // 32x64-tile N=128 GEMMs
    const dim3 gF(DFF / 64, MROWS / 32);          // N=512 GEMM
    const dim3 gD2(2, MROWS / 32);                // w4: K=512 -> N=128
    const dim3 gQKV(6, MROWS / 64);               // fused QKV
    const dim3 gA(SS / 64, BB * HH);              // flash attention

    // ---- self attention: Q,K,V all from x_tgt ----
    gemm_qkv_kernel<<<gQKV, 256>>>(x_tgt, x_tgt, swq, swk, swv, q, k, v);
    attn_mma_kernel<<<gA, 128>>>(q, k, v, attn);
    gemm_kernel<128, 128, 1><<<gD, 128>>>(attn, w1, b1, x_tgt, r1);

    // ---- "cross" attention (faithful quirk): Q from enc_out, K/V from x_tgt ----
    gemm_qkv_kernel<<<gQKV, 256>>>(enc, x_tgt, cwq, cwk, cwv, q, k, v);
    attn_mma_kernel<<<gA, 128>>>(q, k, v, attn);
    gemm_kernel<128, 128, 1><<<gD, 128>>>(attn, w2, b2, r1, r2);

    // ---- norm + FFN ----
    ln_kernel<<<MROWS / 8, 256>>>(r2, ln);
    gemm_kernel<128, 512, 2><<<gF, 128>>>(ln, w3, b3, nullptr, h);   // relu
    gemm_kernel<512, 128, 1><<<gD2, 128>>>(h, w4, b4, r2, out);
}

// round 4
// speedup vs baseline: 2.6903x; 1.1614x over previous
#include <cuda_runtime.h>
#include <cuda_bf16.h>

// Problem constants
#define BB 2
#define SS 2048
#define DD 128
#define HH 8
#define HDIM 16
#define DFF 512
#define MROWS (BB*SS)     // 4096

// ---------------- scratch (device globals; no allocation allowed) -------------
__device__ float g_q[BB*HH*SS*HDIM];
__device__ float g_k[BB*HH*SS*HDIM];
__device__ float g_v[BB*HH*SS*HDIM];
__device__ float g_attn[BB*SS*DD];
__device__ float g_r1[BB*SS*DD];
__device__ float g_r2[BB*SS*DD];
__device__ float g_ln[BB*SS*DD];
__device__ float g_h[BB*SS*DFF];

// ---------------- helpers -----------------------------------------------------
__device__ __forceinline__ unsigned pack_bf16x2(float lo, float hi) {
    unsigned r;
    asm("cvt.rn.bf16x2.f32 %0, %1, %2;" : "=r"(r) : "f"(hi), "f"(lo));
    return r;
}
__device__ __forceinline__ float ex2(float x) {
    float y;
    asm("ex2.approx.ftz.f32 %0, %1;" : "=f"(y) : "f"(x));
    return y;
}
__device__ __forceinline__ unsigned tf32(float x) {
    unsigned r;
    asm("cvt.rna.tf32.f32 %0, %1;" : "=r"(r) : "f"(x));
    return r;
}
__device__ __forceinline__ void mma_bf16(
    float& c0, float& c1, float& c2, float& c3,
    unsigned a0, unsigned a1, unsigned a2, unsigned a3,
    unsigned b0, unsigned b1)
{
    asm("mma.sync.aligned.m16n8k16.row.col.f32.bf16.bf16.f32 "
        "{%0,%1,%2,%3},{%4,%5,%6,%7},{%8,%9},{%0,%1,%2,%3};"
        : "+f"(c0), "+f"(c1), "+f"(c2), "+f"(c3)
        : "r"(a0), "r"(a1), "r"(a2), "r"(a3), "r"(b0), "r"(b1));
}
__device__ __forceinline__ void mma_tf32(
    float& c0, float& c1, float& c2, float& c3,
    unsigned a0, unsigned a1, unsigned a2, unsigned a3,
    unsigned b0, unsigned b1)
{
    asm("mma.sync.aligned.m16n8k8.row.col.f32.tf32.tf32.f32 "
        "{%0,%1,%2,%3},{%4,%5,%6,%7},{%8,%9},{%0,%1,%2,%3};"
        : "+f"(c0), "+f"(c1), "+f"(c2), "+f"(c3)
        : "r"(a0), "r"(a1), "r"(a2), "r"(a3), "r"(b0), "r"(b1));
}

// ---------------- tf32 tensor-core GEMM ---------------------------------------
// out = A(MxK) @ W(KxN) + epilogue.  Block tile 64 x BN, 4 warps (16 x BN each),
// k-step 16 (2 x m16n8k8).  Smem strides (20 / 72 / 40 words) make both A-frag
// (20g+t) and B-frag (8t+g) LDS patterns hit all 32 banks exactly once.
// EPI: 0 plain  1 +bias+res  2 relu(+bias)
template<int K, int N, int BN, int EPI>
__global__ void __launch_bounds__(128) gemm_tc_kernel(
    const float* __restrict__ A, const float* __restrict__ W,
    const float* __restrict__ bias, const float* __restrict__ res,
    float* __restrict__ out)
{
    constexpr int WSTR = (BN == 64) ? 72 : 40;
    constexpr int NT = BN / 8;
    __shared__ unsigned As[64][20];
    __shared__ unsigned Ws[16][WSTR];
    const int tid = threadIdx.x, warp = tid >> 5, lane = tid & 31;
    const int g = lane >> 2, t = lane & 3;
    const int bm = blockIdx.y * 64, bn = blockIdx.x * BN;

    float acc[NT][4] = {};

    for (int kt = 0; kt < K; kt += 16) {
        // A tile 64x16 (fp32 -> tf32)
#pragma unroll
        for (int i = 0; i < 2; i++) {
            int idx = tid * 2 + i;                 // 0..255
            int row = idx >> 2, kc = (idx & 3) * 4;
            float4 a4 = *(const float4*)&A[(size_t)(bm + row) * K + kt + kc];
            As[row][kc + 0] = tf32(a4.x); As[row][kc + 1] = tf32(a4.y);
            As[row][kc + 2] = tf32(a4.z); As[row][kc + 3] = tf32(a4.w);
        }
        // W tile 16xBN
#pragma unroll
        for (int i = 0; i < BN / 32; i++) {
            int idx = tid * (BN / 32) + i;
            int row = idx / (BN / 4), c = (idx % (BN / 4)) * 4;
            float4 w4 = *(const float4*)&W[(size_t)(kt + row) * N + bn + c];
            Ws[row][c + 0] = tf32(w4.x); Ws[row][c + 1] = tf32(w4.y);
            Ws[row][c + 2] = tf32(w4.z); Ws[row][c + 3] = tf32(w4.w);
        }
        __syncthreads();
#pragma unroll
        for (int kb = 0; kb < 16; kb += 8) {
            unsigned a0 = As[warp * 16 + g][kb + t];
            unsigned a1 = As[warp * 16 + 8 + g][kb + t];
            unsigned a2 = As[warp * 16 + g][kb + t + 4];
            unsigned a3 = As[warp * 16 + 8 + g][kb + t + 4];
#pragma unroll
            for (int j = 0; j < NT; j++) {
                unsigned b0 = Ws[kb + t][j * 8 + g];
                unsigned b1 = Ws[kb + t + 4][j * 8 + g];
                mma_tf32(acc[j][0], acc[j][1], acc[j][2], acc[j][3],
                         a0, a1, a2, a3, b0, b1);
            }
        }
        __syncthreads();
    }

    const int r0 = bm + warp * 16 + g;
#pragma unroll
    for (int j = 0; j < NT; j++) {
        int c0 = bn + j * 8 + 2 * t;
        if (EPI == 1) {
            float2 bi = *(const float2*)&bias[c0];
            float2 rA = *(const float2*)&res[(size_t)r0 * N + c0];
            float2 rB = *(const float2*)&res[(size_t)(r0 + 8) * N + c0];
            float2 oA = {acc[j][0] + bi.x + rA.x, acc[j][1] + bi.y + rA.y};
            float2 oB = {acc[j][2] + bi.x + rB.x, acc[j][3] + bi.y + rB.y};
            *(float2*)&out[(size_t)r0 * N + c0] = oA;
            *(float2*)&out[(size_t)(r0 + 8) * N + c0] = oB;
        } else if (EPI == 2) {
            float2 bi = *(const float2*)&bias[c0];
            float2 oA = {fmaxf(acc[j][0] + bi.x, 0.f), fmaxf(acc[j][1] + bi.y, 0.f)};
            float2 oB = {fmaxf(acc[j][2] + bi.x, 0.f), fmaxf(acc[j][3] + bi.y, 0.f)};
            *(float2*)&out[(size_t)r0 * N + c0] = oA;
            *(float2*)&out[(size_t)(r0 + 8) * N + c0] = oB;
        } else {
            *(float2*)&out[(size_t)r0 * N + c0] = {acc[j][0], acc[j][1]};
            *(float2*)&out[(size_t)(r0 + 8) * N + c0] = {acc[j][2], acc[j][3]};
        }
    }
}

// ---------------- tf32 fused QKV projection (scatter to head layout) ----------
// grid (6, 64): blockIdx.x>>1 selects {Q,K,V}; Q may use a different A
// (cross-attn quirk).  Scatter col c -> h=c&7, hd=c>>3 into [b][h][s][hd].
__global__ void __launch_bounds__(128) gemm_qkv_tc_kernel(
    const float* __restrict__ Aq, const float* __restrict__ Akv,
    const float* __restrict__ wq, const float* __restrict__ wk,
    const float* __restrict__ wv,
    float* __restrict__ qo, float* __restrict__ ko, float* __restrict__ vo)
{
    const int which = blockIdx.x >> 1;
    const float* A = (which == 0) ? Aq : Akv;
    const float* W = (which == 0) ? wq : ((which == 1) ? wk : wv);
    float* out     = (which == 0) ? qo : ((which == 1) ? ko : vo);

    __shared__ unsigned As[64][20];
    __shared__ unsigned Ws[16][72];
    const int tid = threadIdx.x, warp = tid >> 5, lane = tid & 31;
    const int g = lane >> 2, t = lane & 3;
    const int bm = blockIdx.y * 64, bn = (blockIdx.x & 1) * 64;

    float acc[8][4] = {};

    for (int kt = 0; kt < DD; kt += 16) {
#pragma unroll
        for (int i = 0; i < 2; i++) {
            int idx = tid * 2 + i;
            int row = idx >> 2, kc = (idx & 3) * 4;
            float4 a4 = *(const float4*)&A[(size_t)(bm + row) * DD + kt + kc];
            As[row][kc + 0] = tf32(a4.x); As[row][kc + 1] = tf32(a4.y);
            As[row][kc + 2] = tf32(a4.z); As[row][kc + 3] = tf32(a4.w);
        }
#pragma unroll
        for (int i = 0; i < 2; i++) {
            int idx = tid * 2 + i;
            int row = idx >> 4, c = (idx & 15) * 4;
            float4 w4 = *(const float4*)&W[(size_t)(kt + row) * DD + bn + c];
            Ws[row][c + 0] = tf32(w4.x); Ws[row][c + 1] = tf32(w4.y);
            Ws[row][c + 2] = tf32(w4.z); Ws[row][c + 3] = tf32(w4.w);
        }
        __syncthreads();
#pragma unroll
        for (int kb = 0; kb < 16; kb += 8) {
            unsigned a0 = As[warp * 16 + g][kb + t];
            unsigned a1 = As[warp * 16 + 8 + g][kb + t];
            unsigned a2 = As[warp * 16 + g][kb + t + 4];
            unsigned a3 = As[warp * 16 + 8 + g][kb + t + 4];
#pragma unroll
            for (int j = 0; j < 8; j++) {
                unsigned b0 = Ws[kb + t][j * 8 + g];
                unsigned b1 = Ws[kb + t + 4][j * 8 + g];
                mma_tf32(acc[j][0], acc[j][1], acc[j][2], acc[j][3],
                         a0, a1, a2, a3, b0, b1);
            }
        }
        __syncthreads();
    }

    const int r0 = bm + warp * 16 + g;
    const int bb0 = r0 >> 11, ss0 = r0 & (SS - 1);
    const int r1 = r0 + 8;
    const int bb1 = r1 >> 11, ss1 = r1 & (SS - 1);
#pragma unroll
    for (int j = 0; j < 8; j++) {
#pragma unroll
        for (int u = 0; u < 2; u++) {
            int c = bn + j * 8 + 2 * t + u;
            int hh = c & 7, hd = c >> 3;
            out[(((size_t)(bb0 * HH + hh) * SS) + ss0) * HDIM + hd] = acc[j][u];
            out[(((size_t)(bb1 * HH + hh) * SS) + ss1) * HDIM + hd] = acc[j][2 + u];
        }
    }
}

// ---------------- flash attention with bf16 tensor cores ----------------------
// grid (S/64, B*H), 128 threads (4 warps), each warp owns 16 query rows.
#define VSTRIDE 136

__global__ void __launch_bounds__(128) attn_mma_kernel(
    const float* __restrict__ q, const float* __restrict__ k,
    const float* __restrict__ v, float* __restrict__ out)
{
    __shared__ unsigned Ks[128][8];              // [key][dim-pair] bf16x2
    __shared__ __nv_bfloat16 Vs[16][VSTRIDE];    // [dim][key] transposed, padded
    const int tid = threadIdx.x, w = tid >> 5, lane = tid & 31;
    const int bh = blockIdx.y, b = bh >> 3, h = bh & 7;
    const int g = lane >> 2, c = lane & 3;
    const size_t head = (size_t)bh * SS;
    const int qrow = blockIdx.x * 64 + w * 16;

    const float sc = 0.25f * 1.4426950408889634f;
    unsigned qa[4];
    {
        const float* r0 = q + (head + qrow + g) * HDIM;
        const float* r1 = r0 + 8 * HDIM;
        float2 t;
        t = *(const float2*)(r0 + 2 * c);     qa[0] = pack_bf16x2(t.x * sc, t.y * sc);
        t = *(const float2*)(r1 + 2 * c);     qa[1] = pack_bf16x2(t.x * sc, t.y * sc);
        t = *(const float2*)(r0 + 2 * c + 8); qa[2] = pack_bf16x2(t.x * sc, t.y * sc);
        t = *(const float2*)(r1 + 2 * c + 8); qa[3] = pack_bf16x2(t.x * sc, t.y * sc);
    }

    float o[8] = {0, 0, 0, 0, 0, 0, 0, 0};
    float l0 = 0.f, l1 = 0.f;

    for (int kt = 0; kt < SS / 128; kt++) {
        __syncthreads();
        const float4* ksrc = (const float4*)(k + (head + kt * 128) * HDIM);
        const float4* vsrc = (const float4*)(v + (head + kt * 128) * HDIM);
#pragma unroll
        for (int i = 0; i < 4; i++) {
            int idx = tid + i * 128;
            int key = idx >> 2, f4 = idx & 3;
            float4 t = ksrc[idx];
            Ks[key][f4 * 2]     = pack_bf16x2(t.x, t.y);
            Ks[key][f4 * 2 + 1] = pack_bf16x2(t.z, t.w);
            float4 u = vsrc[idx];
            Vs[f4 * 4 + 0][key] = __float2bfloat16(u.x);
            Vs[f4 * 4 + 1][key] = __float2bfloat16(u.y);
            Vs[f4 * 4 + 2][key] = __float2bfloat16(u.z);
            Vs[f4 * 4 + 3][key] = __float2bfloat16(u.w);
        }
        __syncthreads();

#pragma unroll
        for (int kc = 0; kc < 8; kc++) {
            float s0 = 0, s1 = 0, s2 = 0, s3 = 0, s4 = 0, s5 = 0, s6 = 0, s7 = 0;
            {
                unsigned b0 = Ks[kc * 16 + g][c];
                unsigned b1 = Ks[kc * 16 + g][c + 4];
                mma_bf16(s0, s1, s2, s3, qa[0], qa[1], qa[2], qa[3], b0, b1);
                b0 = Ks[kc * 16 + 8 + g][c];
                b1 = Ks[kc * 16 + 8 + g][c + 4];
                mma_bf16(s4, s5, s6, s7, qa[0], qa[1], qa[2], qa[3], b0, b1);
            }
            float p0 = ex2(s0), p1 = ex2(s1), p2 = ex2(s2), p3 = ex2(s3);
            float p4 = ex2(s4), p5 = ex2(s5), p6 = ex2(s6), p7 = ex2(s7);
            l0 += (p0 + p1) + (p4 + p5);
            l1 += (p2 + p3) + (p6 + p7);
            unsigned A0 = pack_bf16x2(p0, p1);
            unsigned A1 = pack_bf16x2(p2, p3);
            unsigned A2 = pack_bf16x2(p4, p5);
            unsigned A3 = pack_bf16x2(p6, p7);
            unsigned vb0 = *(const unsigned*)&Vs[g][kc * 16 + 2 * c];
            unsigned vb1 = *(const unsigned*)&Vs[g][kc * 16 + 2 * c + 8];
            mma_bf16(o[0], o[1], o[2], o[3], A0, A1, A2, A3, vb0, vb1);
            vb0 = *(const unsigned*)&Vs[8 + g][kc * 16 + 2 * c];
            vb1 = *(const unsigned*)&Vs[8 + g][kc * 16 + 2 * c + 8];
            mma_bf16(o[4], o[5], o[6], o[7], A0, A1, A2, A3, vb0, vb1);
        }
    }

    l0 += __shfl_xor_sync(~0u, l0, 1); l0 += __shfl_xor_sync(~0u, l0, 2);
    l1 += __shfl_xor_sync(~0u, l1, 1); l1 += __shfl_xor_sync(~0u, l1, 2);
    const float inv0 = 1.0f / l0, inv1 = 1.0f / l1;

    float* ob0 = out + ((size_t)(b * SS) + qrow + g) * DD + h;
    float* ob1 = out + ((size_t)(b * SS) + qrow + 8 + g) * DD + h;
    ob0[(2 * c) * HH]     = o[0] * inv0;
    ob0[(2 * c + 1) * HH] = o[1] * inv0;
    ob0[(8 + 2 * c) * HH] = o[4] * inv0;
    ob0[(9 + 2 * c) * HH] = o[5] * inv0;
    ob1[(2 * c) * HH]     = o[2] * inv1;
    ob1[(2 * c + 1) * HH] = o[3] * inv1;
    ob1[(8 + 2 * c) * HH] = o[6] * inv1;
    ob1[(9 + 2 * c) * HH] = o[7] * inv1;
}

// ---------------- custom "layernorm": c / var, var unbiased (N-1) -------------
__global__ void __launch_bounds__(256) ln_kernel(const float* __restrict__ x,
                                                 float* __restrict__ y)
{
    int row  = blockIdx.x * 8 + (threadIdx.x >> 5);
    int lane = threadIdx.x & 31;
    float4 t = ((const float4*)(x + (size_t)row * DD))[lane];
    float s = t.x + t.y + t.z + t.w;
#pragma unroll
    for (int o = 16; o; o >>= 1) s += __shfl_xor_sync(~0u, s, o);
    float m = s * (1.0f / DD);
    float cx = t.x - m, cy = t.y - m, cz = t.z - m, cw = t.w - m;
    float ss = cx * cx + cy * cy + cz * cz + cw * cw;
#pragma unroll
    for (int o = 16; o; o >>= 1) ss += __shfl_xor_sync(~0u, ss, o);
    float inv = (float)(DD - 1) / ss;
    float4 o4 = {cx * inv, cy * inv, cz * inv, cw * inv};
    ((float4*)(y + (size_t)row * DD))[lane] = o4;
}

// ---------------- launch --------------------------------------------------------
extern "C" void kernel_launch(void* const* d_in, const int* in_sizes, int n_in,
                              void* d_out, int out_size) {
    (void)in_sizes; (void)n_in; (void)out_size;
    const float* x_tgt = (const float*)d_in[0];
    const float* enc   = (const float*)d_in[1];
    const float* swq   = (const float*)d_in[2];
    const float* swk   = (const float*)d_in[3];
    const float* swv   = (const float*)d_in[4];
    const float* cwq   = (const float*)d_in[5];
    const float* cwk   = (const float*)d_in[6];
    const float* cwv   = (const float*)d_in[7];
    const float* w1    = (const float*)d_in[8];
    const float* b1    = (const float*)d_in[9];
    const float* w2    = (const float*)d_in[10];
    const float* b2    = (const float*)d_in[11];
    const float* w3    = (const float*)d_in[12];
    const float* b3    = (const float*)d_in[13];
    const float* w4    = (const float*)d_in[14];
    const float* b4    = (const float*)d_in[15];
    float* out = (float*)d_out;

    float *q, *k, *v, *attn, *r1, *r2, *ln, *h;
    cudaGetSymbolAddress((void**)&q,    g_q);
    cudaGetSymbolAddress((void**)&k,    g_k);
    cudaGetSymbolAddress((void**)&v,    g_v);
    cudaGetSymbolAddress((void**)&attn, g_attn);
    cudaGetSymbolAddress((void**)&r1,   g_r1);
    cudaGetSymbolAddress((void**)&r2,   g_r2);
    cudaGetSymbolAddress((void**)&ln,   g_ln);
    cudaGetSymbolAddress((void**)&h,    g_h);

    const dim3 gQKV(6, MROWS / 64);               // fused QKV (tf32 TC)
    const dim3 gEpi(4, MROWS / 64);               // N=128, BN=32
    const dim3 gW3(8, MROWS / 64);                // N=512, BN=64
    const dim3 gW4(4, MROWS / 64);                // K=512 -> N=128, BN=32
    const dim3 gA(SS / 64, BB * HH);              // flash attention

    // ---- self attention: Q,K,V all from x_tgt ----
    gemm_qkv_tc_kernel<<<gQKV, 128>>>(x_tgt, x_tgt, swq, swk, swv, q, k, v);
    attn_mma_kernel<<<gA, 128>>>(q, k, v, attn);
    gemm_tc_kernel<128, 128, 32, 1><<<gEpi, 128>>>(attn, w1, b1, x_tgt, r1);

    // ---- "cross" attention (faithful quirk): Q from enc_out, K/V from x_tgt ----
    gemm_qkv_tc_kernel<<<gQKV, 128>>>(enc, x_tgt, cwq, cwk, cwv, q, k, v);
    attn_mma_kernel<<<gA, 128>>>(q, k, v, attn);
    gemm_tc_kernel<128, 128, 32, 1><<<gEpi, 128>>>(attn, w2, b2, r1, r2);

    // ---- norm + FFN ----
    ln_kernel<<<MROWS / 8, 256>>>(r2, ln);
    gemm_tc_kernel<128, 512, 64, 2><<<gW3, 128>>>(ln, w3, b3, nullptr, h);   // relu
    gemm_tc_kernel<512, 128, 32, 1><<<gW4, 128>>>(h, w4, b4, r2, out);
}